// round 15
// baseline (speedup 1.0000x reference)
#include <cuda_runtime.h>
#include <cfloat>
#include <cstdint>

// Problem constants
#define BATCH 2
#define NPTS  4096
#define NROWS (BATCH * NPTS)   // 8192
#define DD    256
#define CCAT  784              // 256 + 512 + 16
#define FDIM  512
#define JDIM  16
#define KNN   16
#define NEDGE (NROWS * KNN)    // 131072

#define FBK  16
#define A2S  264   // dup-A smem row stride (floats)
#define BSS  132   // B smem row stride (floats)
#define SM_SGEMM (2 * FBK * A2S * 4 + 2 * FBK * BSS * 4)   // 50688 B
#define SM_HGEMM (SM_SGEMM + 16 * 128 * 4)                 // 58880 B

// ---------------- scratch (device globals; no allocation allowed) ----------
__device__ float g_dist[(size_t)BATCH * NPTS * NPTS];   // 134 MB
__device__ float g_xcat[(size_t)NROWS * CCAT];
__device__ float g_u1[(size_t)NROWS * DD];
__device__ float g_v[(size_t)NROWS * DD];
__device__ float g_sq[NROWS];
__device__ int   g_idx[NROWS * KNN];
__device__ float g_b0[(size_t)NROWS * DD];
__device__ float g_b1[(size_t)NROWS * DD];
__device__ float g_b2[(size_t)NROWS * DD];
__device__ float g_b3[(size_t)NROWS * DD];
__device__ float g_b4[(size_t)NROWS * DD];
__device__ float g_b5[(size_t)NROWS * DD];

// ---------------- tile-load helpers ----------------------------------------
__device__ __forceinline__ void ld8(const float* p, float* r) {
    float4 v0 = *(const float4*)p;
    float4 v1 = *(const float4*)(p + 4);
    r[0] = v0.x; r[1] = v0.y; r[2] = v0.z; r[3] = v0.w;
    r[4] = v1.x; r[5] = v1.y; r[6] = v1.z; r[7] = v1.w;
}
__device__ __forceinline__ void ld8_diff(const float* ps, const float* pn, float* r) {
    float4 s0 = *(const float4*)ps;
    float4 s1 = *(const float4*)(ps + 4);
    float4 n0 = *(const float4*)pn;
    float4 n1 = *(const float4*)(pn + 4);
    r[0] = __fsub_rn(s0.x, n0.x); r[1] = __fsub_rn(s0.y, n0.y);
    r[2] = __fsub_rn(s0.z, n0.z); r[3] = __fsub_rn(s0.w, n0.w);
    r[4] = __fsub_rn(s1.x, n1.x); r[5] = __fsub_rn(s1.y, n1.y);
    r[6] = __fsub_rn(s1.z, n1.z); r[7] = __fsub_rn(s1.w, n1.w);
}

#define UNPACK2(lo, hi, v) \
    asm("mov.b64 {%0, %1}, %2;" : "=f"(lo), "=f"(hi) : "l"(v))

// dup-store one A value as (v, v) pair
__device__ __forceinline__ void st_dup(float* p, float v) {
    *(float2*)p = make_float2(v, v);
}

// FMA2 inner-product step, A pre-duplicated in smem (no per-kk MOV dup).
// acc2[i][j4] packs output columns (2*j4, 2*j4+1). Lane-wise IEEE rn —
// bit-identical to scalar fmaf chains, K ascending.
#define COMPUTE_TILE2D(Ab, Bb)                                               \
    _Pragma("unroll")                                                        \
    for (int kk = 0; kk < FBK; kk++) {                                       \
        const float* ar = (Ab) + kk * A2S + ty * 16;                         \
        const float* br = (Bb) + kk * BSS + tx * 8;                          \
        ulonglong2 aq0 = *(const ulonglong2*)(ar);                           \
        ulonglong2 aq1 = *(const ulonglong2*)(ar + 4);                       \
        ulonglong2 aq2 = *(const ulonglong2*)(ar + 8);                       \
        ulonglong2 aq3 = *(const ulonglong2*)(ar + 12);                      \
        ulonglong2 bq0 = *(const ulonglong2*)(br);                           \
        ulonglong2 bq1 = *(const ulonglong2*)(br + 4);                       \
        unsigned long long ad[8] = {aq0.x, aq0.y, aq1.x, aq1.y,              \
                                    aq2.x, aq2.y, aq3.x, aq3.y};             \
        unsigned long long bv[4] = {bq0.x, bq0.y, bq1.x, bq1.y};             \
        _Pragma("unroll")                                                    \
        for (int i = 0; i < 8; i++)                                          \
            _Pragma("unroll")                                                \
            for (int j = 0; j < 4; j++)                                      \
                asm("fma.rn.f32x2 %0, %1, %2, %0;"                           \
                    : "+l"(acc2[i][j]) : "l"(ad[i]), "l"(bv[j]));            \
    }

// ---------------- symmetric dist GEMM (dup-A, FMA2, single-sync) -----------
__global__ __launch_bounds__(256) void dist_sym(
    const float* __restrict__ X, const float* __restrict__ sq,
    float* __restrict__ dist, int K)
{
    int bx = blockIdx.x, by = blockIdx.y;
    if (by > bx) return;
    const float* Xb  = X  + (size_t)blockIdx.z * NPTS * K;
    const float* sqb = sq + (size_t)blockIdx.z * NPTS;
    float* db        = dist + (size_t)blockIdx.z * NPTS * NPTS;

    extern __shared__ float smx[];
    float* A2 = smx;                       // 2 x [FBK][A2S]
    float* Bs = smx + 2 * FBK * A2S;       // 2 x [FBK][BSS]

    int tid = threadIdx.x;
    int tx = tid & 15, ty = tid >> 4;
    int lr = tid >> 1, lk = (tid & 1) * 8;
    int row0 = by * 128, col0 = bx * 128;

    const float* ap = Xb + (size_t)(row0 + lr) * K + lk;
    const float* bp = Xb + (size_t)(col0 + lr) * K + lk;

    unsigned long long acc2[8][4];
#pragma unroll
    for (int i = 0; i < 8; i++)
#pragma unroll
        for (int j = 0; j < 4; j++) acc2[i][j] = 0ULL;

    float pa[8], pb[8];
    ld8(ap, pa); ld8(bp, pb);
#pragma unroll
    for (int i = 0; i < 8; i++) {
        st_dup(A2 + (lk + i) * A2S + 2 * lr, pa[i]);
        Bs[(lk + i) * BSS + lr] = pb[i];
    }
    __syncthreads();

    int buf = 0;
    for (int k0 = 0; k0 < K; k0 += FBK, buf ^= 1) {
        int kn = k0 + FBK;
        if (kn < K) { ld8(ap + kn, pa); ld8(bp + kn, pb); }
        COMPUTE_TILE2D(A2 + buf * FBK * A2S, Bs + buf * FBK * BSS);
        if (kn < K) {
            float* Aw = A2 + (buf ^ 1) * FBK * A2S;
            float* Bw = Bs + (buf ^ 1) * FBK * BSS;
#pragma unroll
            for (int i = 0; i < 8; i++) {
                st_dup(Aw + (lk + i) * A2S + 2 * lr, pa[i]);
                Bw[(lk + i) * BSS + lr] = pb[i];
            }
            __syncthreads();
        }
    }

#pragma unroll
    for (int i = 0; i < 8; i++) {
        int r = row0 + ty * 8 + i;
        float sr = sqb[r];
#pragma unroll
        for (int j4 = 0; j4 < 4; j4++) {
            float d0, d1;
            UNPACK2(d0, d1, acc2[i][j4]);
            int c0 = col0 + tx * 8 + 2 * j4;
            float sc0 = sqb[c0], sc1 = sqb[c0 + 1];
            float t0 = __fmul_rn(2.f, d0), t1 = __fmul_rn(2.f, d1);
            db[(size_t)r * NPTS + c0]     = __fadd_rn(__fsub_rn(sr, t0), sc0);
            db[(size_t)r * NPTS + c0 + 1] = __fadd_rn(__fsub_rn(sr, t1), sc1);
            db[(size_t)c0 * NPTS + r]       = __fadd_rn(__fsub_rn(sc0, t0), sr);
            db[(size_t)(c0 + 1) * NPTS + r] = __fadd_rn(__fsub_rn(sc1, t1), sr);
        }
    }
}

// ---------------- edge H-GEMM: fused gather + u1 init + bias/relu/16-max ---
__global__ __launch_bounds__(256) void hgemm_max(
    const float* __restrict__ x, const float* __restrict__ W2,
    const float* __restrict__ bias, const float* __restrict__ u1,
    const int* __restrict__ idx,
    float* __restrict__ out, const float* __restrict__ res,
    float* __restrict__ outres, int K)
{
    extern __shared__ float smx[];
    float* A2 = smx;
    float* Bs = smx + 2 * FBK * A2S;
    float* pm = Bs + 2 * FBK * BSS;        // [16][128]

    int tid = threadIdx.x;
    int tx = tid & 15, ty = tid >> 4;
    int lr = tid >> 1, lk = (tid & 1) * 8;
    int brow = tid >> 4, bc = (tid & 15) * 8;
    int row0 = blockIdx.y * 128;       // edge rows
    int col0 = blockIdx.x * 128;       // output channels

    int erow = row0 + lr;
    int nodeA = erow >> 4, tA = erow & 15;
    int bb2 = (nodeA >> 12) << 12;
    int srcA = bb2 + idx[nodeA * KNN + tA];
    const float* aps = x + (size_t)srcA * K + lk;
    const float* apn = x + (size_t)nodeA * K + lk;
    const float* bp  = W2 + (size_t)brow * DD + col0 + bc;

    unsigned long long acc2[8][4];
#pragma unroll
    for (int i = 0; i < 8; i++) {
        int node = (row0 + ty * 8 + i) >> 4;
        const unsigned long long* up =
            (const unsigned long long*)&u1[(size_t)node * DD + col0 + tx * 8];
#pragma unroll
        for (int j = 0; j < 4; j++) acc2[i][j] = up[j];
    }

    float pa[8], pb[8];
    ld8_diff(aps, apn, pa);
    ld8(bp, pb);
#pragma unroll
    for (int i = 0; i < 8; i++) st_dup(A2 + (lk + i) * A2S + 2 * lr, pa[i]);
    *(float4*)&Bs[brow * BSS + bc]     = make_float4(pb[0], pb[1], pb[2], pb[3]);
    *(float4*)&Bs[brow * BSS + bc + 4] = make_float4(pb[4], pb[5], pb[6], pb[7]);
    __syncthreads();

    int buf = 0;
    for (int k0 = 0; k0 < K; k0 += FBK, buf ^= 1) {
        int kn = k0 + FBK;
        if (kn < K) {
            ld8_diff(aps + kn, apn + kn, pa);
            ld8(bp + (size_t)kn * DD, pb);
        }
        COMPUTE_TILE2D(A2 + buf * FBK * A2S, Bs + buf * FBK * BSS);
        if (kn < K) {
            float* Aw = A2 + (buf ^ 1) * FBK * A2S;
            float* Bw = Bs + (buf ^ 1) * FBK * BSS;
#pragma unroll
            for (int i = 0; i < 8; i++) st_dup(Aw + (lk + i) * A2S + 2 * lr, pa[i]);
            *(float4*)&Bw[brow * BSS + bc]     = make_float4(pb[0], pb[1], pb[2], pb[3]);
            *(float4*)&Bw[brow * BSS + bc + 4] = make_float4(pb[4], pb[5], pb[6], pb[7]);
            __syncthreads();
        }
    }

    // epilogue: +bias (rounded), relu, per-thread max over own 8 edge rows
#pragma unroll
    for (int j4 = 0; j4 < 4; j4++) {
        int cc0 = tx * 8 + 2 * j4;
        float b0v = bias[col0 + cc0], b1v = bias[col0 + cc0 + 1];
        float mx0 = -FLT_MAX, mx1 = -FLT_MAX;
#pragma unroll
        for (int i = 0; i < 8; i++) {
            float h0, h1;
            UNPACK2(h0, h1, acc2[i][j4]);
            h0 = fmaxf(__fadd_rn(h0, b0v), 0.f);
            h1 = fmaxf(__fadd_rn(h1, b1v), 0.f);
            mx0 = fmaxf(mx0, h0);
            mx1 = fmaxf(mx1, h1);
        }
        pm[ty * 128 + cc0] = mx0;
        pm[ty * 128 + cc0 + 1] = mx1;
    }
    __syncthreads();
    if ((ty & 1) == 0) {
        int node = (row0 >> 4) + (ty >> 1);
#pragma unroll
        for (int j = 0; j < 8; j++) {
            int cc = tx * 8 + j;
            float m = fmaxf(pm[ty * 128 + cc], pm[(ty + 1) * 128 + cc]);
            int col = col0 + cc;
            out[(size_t)node * DD + col] = m;
            if (res) outres[(size_t)node * DD + col] =
                __fadd_rn(m, res[(size_t)node * DD + col]);
        }
    }
}

// ---------------- fast aligned SGEMM (dup-A, FMA2) -------------------------
__global__ __launch_bounds__(256) void sgemm_fast(
    const float* __restrict__ A, const float* __restrict__ B,
    const float* __restrict__ bias, float* __restrict__ C,
    int N, int K, int do_relu)
{
    extern __shared__ float smx[];
    float* A2 = smx;
    float* Bs = smx + 2 * FBK * A2S;

    int tid = threadIdx.x;
    int tx = tid & 15, ty = tid >> 4;
    int lr = tid >> 1, lk = (tid & 1) * 8;
    int brow = tid >> 4, bc = (tid & 15) * 8;
    int row0 = blockIdx.y * 128, col0 = blockIdx.x * 128;

    const float* ap = A + (size_t)(row0 + lr) * K + lk;
    const float* bp = B + (size_t)brow * N + col0 + bc;

    unsigned long long acc2[8][4];
#pragma unroll
    for (int i = 0; i < 8; i++)
#pragma unroll
        for (int j = 0; j < 4; j++) acc2[i][j] = 0ULL;

    float pa[8], pb[8];
    ld8(ap, pa); ld8(bp, pb);
#pragma unroll
    for (int i = 0; i < 8; i++) st_dup(A2 + (lk + i) * A2S + 2 * lr, pa[i]);
    *(float4*)&Bs[brow * BSS + bc]     = make_float4(pb[0], pb[1], pb[2], pb[3]);
    *(float4*)&Bs[brow * BSS + bc + 4] = make_float4(pb[4], pb[5], pb[6], pb[7]);
    __syncthreads();

    int buf = 0;
    for (int k0 = 0; k0 < K; k0 += FBK, buf ^= 1) {
        int kn = k0 + FBK;
        if (kn < K) { ld8(ap + kn, pa); ld8(bp + (size_t)kn * N, pb); }
        COMPUTE_TILE2D(A2 + buf * FBK * A2S, Bs + buf * FBK * BSS);
        if (kn < K) {
            float* Aw = A2 + (buf ^ 1) * FBK * A2S;
            float* Bw = Bs + (buf ^ 1) * FBK * BSS;
#pragma unroll
            for (int i = 0; i < 8; i++) st_dup(Aw + (lk + i) * A2S + 2 * lr, pa[i]);
            *(float4*)&Bw[brow * BSS + bc]     = make_float4(pb[0], pb[1], pb[2], pb[3]);
            *(float4*)&Bw[brow * BSS + bc + 4] = make_float4(pb[4], pb[5], pb[6], pb[7]);
            __syncthreads();
        }
    }

#pragma unroll
    for (int i = 0; i < 8; i++) {
        int r = row0 + ty * 8 + i;
#pragma unroll
        for (int j4 = 0; j4 < 4; j4++) {
            float v0, v1;
            UNPACK2(v0, v1, acc2[i][j4]);
            int c0 = col0 + tx * 8 + 2 * j4;
            if (bias) {
                v0 = __fadd_rn(v0, bias[c0]);
                v1 = __fadd_rn(v1, bias[c0 + 1]);
            }
            if (do_relu) { v0 = fmaxf(v0, 0.f); v1 = fmaxf(v1, 0.f); }
            C[(size_t)r * N + c0]     = v0;
            C[(size_t)r * N + c0 + 1] = v1;
        }
    }
}

// ---------------- general SGEMM (bounds-checked; only K=3 coords layer) ----
#define BK 8
__global__ __launch_bounds__(256) void sgemm_nn(
    const float* __restrict__ A, const float* __restrict__ B,
    const float* __restrict__ bias, float* __restrict__ C,
    int M, int N, int K, int do_relu)
{
    __shared__ float As[BK][128];
    __shared__ float Bs[BK][128];
    int tid = threadIdx.x;
    int row0 = blockIdx.y * 128;
    int col0 = blockIdx.x * 128;
    int tx = tid & 15, ty = tid >> 4;
    int arow = tid >> 1, ac0 = (tid & 1) * 4;
    int brow = tid >> 5, bc0 = (tid & 31) * 4;

    float acc[8][8];
#pragma unroll
    for (int i = 0; i < 8; i++)
#pragma unroll
        for (int j = 0; j < 8; j++) acc[i][j] = 0.f;

    for (int k0 = 0; k0 < K; k0 += BK) {
#pragma unroll
        for (int i = 0; i < 4; i++) {
            int gr = row0 + arow, gc = k0 + ac0 + i;
            As[ac0 + i][arow] = (gr < M && gc < K) ? A[(size_t)gr * K + gc] : 0.f;
        }
#pragma unroll
        for (int i = 0; i < 4; i++) {
            int gr = k0 + brow, gc = col0 + bc0 + i;
            Bs[brow][bc0 + i] = (gr < K && gc < N) ? B[(size_t)gr * N + gc] : 0.f;
        }
        __syncthreads();
#pragma unroll
        for (int kk = 0; kk < BK; kk++) {
            float a[8], b[8];
#pragma unroll
            for (int i = 0; i < 8; i++) a[i] = As[kk][ty * 8 + i];
#pragma unroll
            for (int j = 0; j < 8; j++) b[j] = Bs[kk][tx * 8 + j];
#pragma unroll
            for (int i = 0; i < 8; i++)
#pragma unroll
                for (int j = 0; j < 8; j++)
                    acc[i][j] = fmaf(a[i], b[j], acc[i][j]);
        }
        __syncthreads();
    }

#pragma unroll
    for (int i = 0; i < 8; i++) {
        int r = row0 + ty * 8 + i;
        if (r >= M) continue;
#pragma unroll
        for (int j = 0; j < 8; j++) {
            int c = col0 + tx * 8 + j;
            if (c >= N) continue;
            float vv = acc[i][j];
            if (bias) vv = __fadd_rn(vv, bias[c]);
            if (do_relu) vv = fmaxf(vv, 0.f);
            C[(size_t)r * N + c] = vv;
        }
    }
}

// ---------------- row squared norm (same rounding tree, 16 threads/row) ----
__global__ void row_sq_cpu(const float* __restrict__ x, float* __restrict__ sq, int K)
{
    int g = blockIdx.x * 256 + threadIdx.x;
    int row = g >> 4;
    if (row >= NROWS) return;
    int j = g & 15;
    const float* xr = x + (size_t)row * K;
    float a = 0.f;
    for (int i = 0; i < K; i += 16) {
        float v = xr[i + j];
        a = __fadd_rn(a, __fmul_rn(v, v));
    }
    unsigned lane = threadIdx.x & 31;
    unsigned base = lane & 16u;
    float b1 = __shfl_sync(0xffffffffu, a, base + ((j + 4) & 15));
    float b2 = __shfl_sync(0xffffffffu, a, base + ((j + 8) & 15));
    float b3 = __shfl_sync(0xffffffffu, a, base + ((j + 12) & 15));
    float t = __fadd_rn(__fadd_rn(__fadd_rn(a, b1), b2), b3);
    float tp = __shfl_sync(0xffffffffu, t, base + ((j + 2) & 15));
    float u = __fadd_rn(t, tp);
    float up = __shfl_sync(0xffffffffu, u, base + 1);
    if (j == 0) sq[row] = __fadd_rn(u, up);
}

// ---------------- top-16 smallest per row (one warp per row, proven) -------
__global__ __launch_bounds__(256) void knn_topk(
    const float* __restrict__ dist, int* __restrict__ idx)
{
    int gw = (blockIdx.x * 256 + threadIdx.x) >> 5;
    int lane = threadIdx.x & 31;
    if (gw >= NROWS) return;
    const float* dr = dist + (size_t)gw * NPTS;

    float ld[KNN]; int li[KNN];
#pragma unroll
    for (int i = 0; i < KNN; i++) { ld[i] = FLT_MAX; li[i] = 0x7fffffff; }

    for (int j = lane; j < NPTS; j += 32) {
        float d = dr[j];
        if (d < ld[KNN - 1]) {
            ld[KNN - 1] = d; li[KNN - 1] = j;
#pragma unroll
            for (int p = KNN - 1; p > 0; p--) {
                if (ld[p] < ld[p - 1]) {
                    float tf = ld[p]; ld[p] = ld[p - 1]; ld[p - 1] = tf;
                    int ti = li[p]; li[p] = li[p - 1]; li[p - 1] = ti;
                }
            }
        }
    }

    int* orow = idx + gw * KNN;
    for (int t = 0; t < KNN; t++) {
        float mv = ld[0]; int mi = li[0];
#pragma unroll
        for (int o = 16; o; o >>= 1) {
            float ov = __shfl_xor_sync(0xffffffffu, mv, o);
            int   oi = __shfl_xor_sync(0xffffffffu, mi, o);
            if (ov < mv || (ov == mv && oi < mi)) { mv = ov; mi = oi; }
        }
        if (lane == 0) orow[t] = mi;
        if (li[0] == mi) {
#pragma unroll
            for (int p = 0; p < KNN - 1; p++) { ld[p] = ld[p + 1]; li[p] = li[p + 1]; }
            ld[KNN - 1] = FLT_MAX; li[KNN - 1] = 0x7fffffff;
        }
    }
}

// ---------------- u/v aggregation for the FINAL conv (selection-free) ------
// out[n][d] = max_t relu(u1[n][d] + (v[src][d]-v[n][d]) + b[d]).
// Rounding differs from the literal edge chain by ~1e-5 relative, but this
// conv's output feeds only dense heads (no further kNN), so the deviation
// propagates continuously.
__global__ __launch_bounds__(256) void ec_agg_uv(
    const float* __restrict__ u1, const float* __restrict__ v,
    const float* __restrict__ bias, const int* __restrict__ idx,
    float* __restrict__ out, const float* __restrict__ res,
    float* __restrict__ outres)
{
    int row = blockIdx.x;
    int d = threadIdx.x;
    int bb = (row >> 12) << 12;
    __shared__ int sidx[KNN];
    if (d < KNN) sidx[d] = idx[row * KNN + d] + bb;
    __syncthreads();
    float vn = v[(size_t)row * DD + d];
    float uu = u1[(size_t)row * DD + d];
    float bd = bias[d];
    float m = -FLT_MAX;
#pragma unroll
    for (int t = 0; t < KNN; t++) {
        float vs = v[(size_t)sidx[t] * DD + d];
        float h = fmaxf(__fadd_rn(__fadd_rn(uu, __fsub_rn(vs, vn)), bd), 0.f);
        m = fmaxf(m, h);
    }
    out[(size_t)row * DD + d] = m;
    if (res) outres[(size_t)row * DD + d] = __fadd_rn(m, res[(size_t)row * DD + d]);
}

// ---------------- concat [x2(256) | feat(512) | joint(16)] ------------------
__global__ void concat_kernel(const float* __restrict__ x2, const float* __restrict__ feat,
                              const float* __restrict__ joint, float* __restrict__ xcat)
{
    size_t i = (size_t)blockIdx.x * 256 + threadIdx.x;
    if (i >= (size_t)NROWS * CCAT) return;
    int row = (int)(i / CCAT);
    int c = (int)(i % CCAT);
    float v;
    if (c < DD)            v = x2[(size_t)row * DD + c];
    else if (c < DD + FDIM) v = feat[(size_t)row * FDIM + (c - DD)];
    else                    v = joint[(size_t)row * JDIM + (c - DD - FDIM)];
    xcat[i] = v;
}

// ---------------- small-N head GEMM (N = 3 or 1), relu ----------------------
__global__ void head_gemm(const float* __restrict__ A, const float* __restrict__ W,
                          const float* __restrict__ bias, float* __restrict__ out, int Nout)
{
    int warp = (blockIdx.x * 256 + threadIdx.x) >> 5;
    int lane = threadIdx.x & 31;
    if (warp >= NROWS) return;
    const float* a = A + (size_t)warp * DD;
    for (int oc = 0; oc < Nout; oc++) {
        float s = 0.f;
        for (int c = lane; c < DD; c += 32) s = fmaf(a[c], W[(size_t)c * Nout + oc], s);
#pragma unroll
        for (int o = 16; o; o >>= 1) s += __shfl_xor_sync(0xffffffffu, s, o);
        if (lane == 0) out[(size_t)warp * Nout + oc] = fmaxf(__fadd_rn(s, bias[oc]), 0.f);
    }
}

// ---------------- host-side orchestration -----------------------------------
static void run_edge_conv(const float* x, int C, const float* w, const float* bias,
                          float* sq, float* dist, int* idx, float* u1, float* v,
                          float* out, const float* res, float* outres, int use_uv)
{
    sgemm_fast<<<dim3(DD / 128, NROWS / 128), 256, SM_SGEMM>>>(x, w, nullptr, u1, DD, C, 0);
    row_sq_cpu<<<NROWS * 16 / 256, 256>>>(x, sq, C);
    dist_sym<<<dim3(32, 32, BATCH), 256, SM_SGEMM>>>(x, sq, dist, C);
    knn_topk<<<NROWS * 32 / 256, 256>>>(dist, idx);
    if (use_uv) {
        sgemm_fast<<<dim3(DD / 128, NROWS / 128), 256, SM_SGEMM>>>(
            x, w + (size_t)C * DD, nullptr, v, DD, C, 0);
        ec_agg_uv<<<NROWS, 256>>>(u1, v, bias, idx, out, res, outres);
    } else {
        hgemm_max<<<dim3(DD / 128, NEDGE / 128), 256, SM_HGEMM>>>(
            x, w + (size_t)C * DD, bias, u1, idx, out, res, outres, C);
    }
}

extern "C" void kernel_launch(void* const* d_in, const int* in_sizes, int n_in,
                              void* d_out, int out_size)
{
    const float* coords = (const float*)d_in[0];
    const float* feat   = (const float*)d_in[1];
    const float* joint  = (const float*)d_in[2];
    const float* w_h1 = (const float*)d_in[3];  const float* b_h1 = (const float*)d_in[4];
    const float* w_h2 = (const float*)d_in[5];  const float* b_h2 = (const float*)d_in[6];
    const float* w_e1 = (const float*)d_in[7];  const float* b_e1 = (const float*)d_in[8];
    const float* w_e2 = (const float*)d_in[9];  const float* b_e2 = (const float*)d_in[10];
    const float* w_h3 = (const float*)d_in[11]; const float* b_h3 = (const float*)d_in[12];
    const float* w_c1 = (const float*)d_in[13]; const float* b_c1 = (const float*)d_in[14];
    const float* w_c2 = (const float*)d_in[15]; const float* b_c2 = (const float*)d_in[16];
    const float* w_c3 = (const float*)d_in[17]; const float* b_c3 = (const float*)d_in[18];
    const float* w_h4 = (const float*)d_in[19]; const float* b_h4 = (const float*)d_in[20];
    const float* w_o1 = (const float*)d_in[21]; const float* b_o1 = (const float*)d_in[22];
    const float* w_h5 = (const float*)d_in[23]; const float* b_h5 = (const float*)d_in[24];
    const float* w_o2 = (const float*)d_in[25]; const float* b_o2 = (const float*)d_in[26];
    float* out = (float*)d_out;

    static int smem_set = 0;
    if (!smem_set) {
        cudaFuncSetAttribute(sgemm_fast, cudaFuncAttributeMaxDynamicSharedMemorySize, SM_SGEMM);
        cudaFuncSetAttribute(dist_sym,   cudaFuncAttributeMaxDynamicSharedMemorySize, SM_SGEMM);
        cudaFuncSetAttribute(hgemm_max,  cudaFuncAttributeMaxDynamicSharedMemorySize, SM_HGEMM);
        smem_set = 1;
    }

    void* p;
    cudaGetSymbolAddress(&p, g_dist); float* dist = (float*)p;
    cudaGetSymbolAddress(&p, g_xcat); float* xcat = (float*)p;
    cudaGetSymbolAddress(&p, g_u1);   float* u1   = (float*)p;
    cudaGetSymbolAddress(&p, g_v);    float* v    = (float*)p;
    cudaGetSymbolAddress(&p, g_sq);   float* sq   = (float*)p;
    cudaGetSymbolAddress(&p, g_idx);  int*   idx  = (int*)p;
    cudaGetSymbolAddress(&p, g_b0);   float* b0   = (float*)p;
    cudaGetSymbolAddress(&p, g_b1);   float* b1   = (float*)p;
    cudaGetSymbolAddress(&p, g_b2);   float* b2   = (float*)p;
    cudaGetSymbolAddress(&p, g_b3);   float* b3   = (float*)p;
    cudaGetSymbolAddress(&p, g_b4);   float* b4   = (float*)p;
    cudaGetSymbolAddress(&p, g_b5);   float* b5   = (float*)p;

    // x1 = relu(coords @ w_h1 + b_h1) ; x2 = relu(x1 @ w_h2 + b_h2)
    sgemm_nn<<<dim3(2, 64), 256>>>(coords, w_h1, b_h1, b0, NROWS, DD, 3, 1);
    sgemm_fast<<<dim3(2, 64), 256, SM_SGEMM>>>(b0, w_h2, b_h2, b1, DD, DD, 1);

    // xcat = [x2 | feat | joint]  (8192 x 784)
    concat_kernel<<<(int)(((size_t)NROWS * CCAT + 255) / 256), 256>>>(b1, feat, joint, xcat);

    // EdgeConvE 1 (C=784) -> b0
    run_edge_conv(xcat, CCAT, w_e1, b_e1, sq, dist, idx, u1, v, b0, nullptr, nullptr, 0);
    // EdgeConvE 2 (C=256) -> b1
    run_edge_conv(b0, DD, w_e2, b_e2, sq, dist, idx, u1, v, b1, nullptr, nullptr, 0);

    // x3 = relu(b1 @ w_h3 + b_h3) -> b2
    sgemm_fast<<<dim3(2, 64), 256, SM_SGEMM>>>(b1, w_h3, b_h3, b2, DD, DD, 1);

    // e1 = edgeconv(x3, c1) -> b3
    run_edge_conv(b2, DD, w_c1, b_c1, sq, dist, idx, u1, v, b3, nullptr, nullptr, 0);
    // e2 = edgeconv(e1, c2) -> b4 ; xa = e2 + e1 -> b5
    run_edge_conv(b3, DD, w_c2, b_c2, sq, dist, idx, u1, v, b4, b3, b5, 0);
    // e3 = edgeconv(xa, c3) -> b2 ; xb = e3 + e2 -> b0   (FINAL conv: u/v ok)
    run_edge_conv(b5, DD, w_c3, b_c3, sq, dist, idx, u1, v, b2, b4, b0, 1);

    // out1 = relu(relu(xb @ w_h4 + b_h4) @ w_o1 + b_o1)   [8192 x 3]
    sgemm_fast<<<dim3(2, 64), 256, SM_SGEMM>>>(b0, w_h4, b_h4, b1, DD, DD, 1);
    head_gemm<<<NROWS * 32 / 256, 256>>>(b1, w_o1, b_o1, out, 3);

    // out2 = relu(relu(xb @ w_h5 + b_h5) @ w_o2 + b_o2)   [8192 x 1]
    sgemm_fast<<<dim3(2, 64), 256, SM_SGEMM>>>(b0, w_h5, b_h5, b3, DD, DD, 1);
    head_gemm<<<NROWS * 32 / 256, 256>>>(b3, w_o2, b_o2, out + (size_t)NROWS * 3, 1);
}

// round 16
// speedup vs baseline: 1.1699x; 1.1699x over previous
#include <cuda_runtime.h>
#include <cfloat>
#include <cstdint>

// Problem constants
#define BATCH 2
#define NPTS  4096
#define NROWS (BATCH * NPTS)   // 8192
#define DD    256
#define CCAT  784              // 256 + 512 + 16
#define FDIM  512
#define JDIM  16
#define KNN   16
#define NEDGE (NROWS * KNN)    // 131072

#define FBK  16
#define SPAD 132

// ---------------- scratch (device globals; no allocation allowed) ----------
__device__ float g_dist[(size_t)BATCH * NPTS * NPTS];   // 134 MB
__device__ float g_xcat[(size_t)NROWS * CCAT];
__device__ float g_u1[(size_t)NROWS * DD];
__device__ float g_v[(size_t)NROWS * DD];
__device__ float g_sq[NROWS];
__device__ int   g_idx[NROWS * KNN];
__device__ float g_b0[(size_t)NROWS * DD];
__device__ float g_b1[(size_t)NROWS * DD];
__device__ float g_b2[(size_t)NROWS * DD];
__device__ float g_b3[(size_t)NROWS * DD];
__device__ float g_b4[(size_t)NROWS * DD];
__device__ float g_b5[(size_t)NROWS * DD];

// ---------------- tile-load helpers ----------------------------------------
__device__ __forceinline__ void ld8(const float* p, float* r) {
    float4 v0 = *(const float4*)p;
    float4 v1 = *(const float4*)(p + 4);
    r[0] = v0.x; r[1] = v0.y; r[2] = v0.z; r[3] = v0.w;
    r[4] = v1.x; r[5] = v1.y; r[6] = v1.z; r[7] = v1.w;
}
__device__ __forceinline__ void ld8_diff(const float* ps, const float* pn, float* r) {
    float4 s0 = *(const float4*)ps;
    float4 s1 = *(const float4*)(ps + 4);
    float4 n0 = *(const float4*)pn;
    float4 n1 = *(const float4*)(pn + 4);
    r[0] = __fsub_rn(s0.x, n0.x); r[1] = __fsub_rn(s0.y, n0.y);
    r[2] = __fsub_rn(s0.z, n0.z); r[3] = __fsub_rn(s0.w, n0.w);
    r[4] = __fsub_rn(s1.x, n1.x); r[5] = __fsub_rn(s1.y, n1.y);
    r[6] = __fsub_rn(s1.z, n1.z); r[7] = __fsub_rn(s1.w, n1.w);
}

#define UNPACK2(lo, hi, v) \
    asm("mov.b64 {%0, %1}, %2;" : "=f"(lo), "=f"(hi) : "l"(v))

// FMA2 inner-product step (R13 proven core): A scalar in smem, duplicated
// into both lanes via mov.b64 (ALU pipe, parallel to FMA pipe). acc2[i][j4]
// packs output columns (2*j4, 2*j4+1). Lane-wise IEEE rn — bit-identical to
// scalar fmaf chains, K ascending.
#define COMPUTE_TILE2(AsB, BsB)                                               \
    _Pragma("unroll")                                                         \
    for (int kk = 0; kk < FBK; kk++) {                                        \
        float4 av0 = *(const float4*)&AsB[kk][ty * 8];                        \
        float4 av1 = *(const float4*)&AsB[kk][ty * 8 + 4];                    \
        ulonglong2 bq0 = *(const ulonglong2*)&BsB[kk][tx * 8];                \
        ulonglong2 bq1 = *(const ulonglong2*)&BsB[kk][tx * 8 + 4];            \
        unsigned long long bb[4] = {bq0.x, bq0.y, bq1.x, bq1.y};              \
        float a[8] = {av0.x, av0.y, av0.z, av0.w, av1.x, av1.y, av1.z, av1.w};\
        _Pragma("unroll")                                                     \
        for (int i = 0; i < 8; i++) {                                         \
            unsigned long long ad;                                            \
            asm("mov.b64 %0, {%1, %1};" : "=l"(ad) : "f"(a[i]));              \
            _Pragma("unroll")                                                 \
            for (int j = 0; j < 4; j++)                                       \
                asm("fma.rn.f32x2 %0, %1, %2, %0;"                            \
                    : "+l"(acc2[i][j]) : "l"(ad), "l"(bb[j]));                \
        }                                                                     \
    }

// ---------------- symmetric dist GEMM (FMA2, single-sync double buffer) ----
__global__ __launch_bounds__(256) void dist_sym(
    const float* __restrict__ X, const float* __restrict__ sq,
    float* __restrict__ dist, int K)
{
    int bx = blockIdx.x, by = blockIdx.y;
    if (by > bx) return;
    const float* Xb  = X  + (size_t)blockIdx.z * NPTS * K;
    const float* sqb = sq + (size_t)blockIdx.z * NPTS;
    float* db        = dist + (size_t)blockIdx.z * NPTS * NPTS;

    __shared__ float As[2][FBK][SPAD];
    __shared__ float Bs[2][FBK][SPAD];
    int tid = threadIdx.x;
    int tx = tid & 15, ty = tid >> 4;
    int lr = tid >> 1, lk = (tid & 1) * 8;
    int row0 = by * 128, col0 = bx * 128;

    const float* ap = Xb + (size_t)(row0 + lr) * K + lk;
    const float* bp = Xb + (size_t)(col0 + lr) * K + lk;

    unsigned long long acc2[8][4];
#pragma unroll
    for (int i = 0; i < 8; i++)
#pragma unroll
        for (int j = 0; j < 4; j++) acc2[i][j] = 0ULL;

    float pa[8], pb[8];
    ld8(ap, pa); ld8(bp, pb);
#pragma unroll
    for (int i = 0; i < 8; i++) { As[0][lk + i][lr] = pa[i]; Bs[0][lk + i][lr] = pb[i]; }
    __syncthreads();

    int buf = 0;
    for (int k0 = 0; k0 < K; k0 += FBK, buf ^= 1) {
        int kn = k0 + FBK;
        if (kn < K) { ld8(ap + kn, pa); ld8(bp + kn, pb); }
        if (buf == 0) { COMPUTE_TILE2(As[0], Bs[0]); } else { COMPUTE_TILE2(As[1], Bs[1]); }
        if (kn < K) {
#pragma unroll
            for (int i = 0; i < 8; i++) {
                As[buf ^ 1][lk + i][lr] = pa[i];
                Bs[buf ^ 1][lk + i][lr] = pb[i];
            }
            __syncthreads();
        }
    }

#pragma unroll
    for (int i = 0; i < 8; i++) {
        int r = row0 + ty * 8 + i;
        float sr = sqb[r];
#pragma unroll
        for (int j4 = 0; j4 < 4; j4++) {
            float d0, d1;
            UNPACK2(d0, d1, acc2[i][j4]);
            int c0 = col0 + tx * 8 + 2 * j4;
            float sc0 = sqb[c0], sc1 = sqb[c0 + 1];
            float t0 = __fmul_rn(2.f, d0), t1 = __fmul_rn(2.f, d1);
            db[(size_t)r * NPTS + c0]     = __fadd_rn(__fsub_rn(sr, t0), sc0);
            db[(size_t)r * NPTS + c0 + 1] = __fadd_rn(__fsub_rn(sr, t1), sc1);
            db[(size_t)c0 * NPTS + r]       = __fadd_rn(__fsub_rn(sc0, t0), sr);
            db[(size_t)(c0 + 1) * NPTS + r] = __fadd_rn(__fsub_rn(sc1, t1), sr);
        }
    }
}

// ---------------- edge H-GEMM: fused gather + u1 init + bias/relu/16-max ---
__global__ __launch_bounds__(256) void hgemm_max(
    const float* __restrict__ x, const float* __restrict__ W2,
    const float* __restrict__ bias, const float* __restrict__ u1,
    const int* __restrict__ idx,
    float* __restrict__ out, const float* __restrict__ res,
    float* __restrict__ outres, int K)
{
    __shared__ float As[2][FBK][SPAD];
    __shared__ float Bs[2][FBK][SPAD];
    __shared__ float pm[16][128];

    int tid = threadIdx.x;
    int tx = tid & 15, ty = tid >> 4;
    int lr = tid >> 1, lk = (tid & 1) * 8;
    int brow = tid >> 4, bc = (tid & 15) * 8;
    int row0 = blockIdx.y * 128;       // edge rows
    int col0 = blockIdx.x * 128;       // output channels

    int erow = row0 + lr;
    int nodeA = erow >> 4, tA = erow & 15;
    int bb2 = (nodeA >> 12) << 12;
    int srcA = bb2 + idx[nodeA * KNN + tA];
    const float* aps = x + (size_t)srcA * K + lk;
    const float* apn = x + (size_t)nodeA * K + lk;
    const float* bp  = W2 + (size_t)brow * DD + col0 + bc;

    unsigned long long acc2[8][4];
#pragma unroll
    for (int i = 0; i < 8; i++) {
        int node = (row0 + ty * 8 + i) >> 4;
        const unsigned long long* up =
            (const unsigned long long*)&u1[(size_t)node * DD + col0 + tx * 8];
#pragma unroll
        for (int j = 0; j < 4; j++) acc2[i][j] = up[j];
    }

    float pa[8], pb[8];
    ld8_diff(aps, apn, pa);
    ld8(bp, pb);
#pragma unroll
    for (int i = 0; i < 8; i++) As[0][lk + i][lr] = pa[i];
    *(float4*)&Bs[0][brow][bc]     = make_float4(pb[0], pb[1], pb[2], pb[3]);
    *(float4*)&Bs[0][brow][bc + 4] = make_float4(pb[4], pb[5], pb[6], pb[7]);
    __syncthreads();

    int buf = 0;
    for (int k0 = 0; k0 < K; k0 += FBK, buf ^= 1) {
        int kn = k0 + FBK;
        if (kn < K) {
            ld8_diff(aps + kn, apn + kn, pa);
            ld8(bp + (size_t)kn * DD, pb);
        }
        if (buf == 0) { COMPUTE_TILE2(As[0], Bs[0]); } else { COMPUTE_TILE2(As[1], Bs[1]); }
        if (kn < K) {
#pragma unroll
            for (int i = 0; i < 8; i++) As[buf ^ 1][lk + i][lr] = pa[i];
            *(float4*)&Bs[buf ^ 1][brow][bc]     = make_float4(pb[0], pb[1], pb[2], pb[3]);
            *(float4*)&Bs[buf ^ 1][brow][bc + 4] = make_float4(pb[4], pb[5], pb[6], pb[7]);
            __syncthreads();
        }
    }

    // epilogue: +bias (rounded), relu, per-thread max over own 8 edge rows
#pragma unroll
    for (int j4 = 0; j4 < 4; j4++) {
        int cc0 = tx * 8 + 2 * j4;
        float b0v = bias[col0 + cc0], b1v = bias[col0 + cc0 + 1];
        float mx0 = -FLT_MAX, mx1 = -FLT_MAX;
#pragma unroll
        for (int i = 0; i < 8; i++) {
            float h0, h1;
            UNPACK2(h0, h1, acc2[i][j4]);
            h0 = fmaxf(__fadd_rn(h0, b0v), 0.f);
            h1 = fmaxf(__fadd_rn(h1, b1v), 0.f);
            mx0 = fmaxf(mx0, h0);
            mx1 = fmaxf(mx1, h1);
        }
        pm[ty][cc0] = mx0;
        pm[ty][cc0 + 1] = mx1;
    }
    __syncthreads();
    if ((ty & 1) == 0) {
        int node = (row0 >> 4) + (ty >> 1);
#pragma unroll
        for (int j = 0; j < 8; j++) {
            int cc = tx * 8 + j;
            float m = fmaxf(pm[ty][cc], pm[ty + 1][cc]);
            int col = col0 + cc;
            out[(size_t)node * DD + col] = m;
            if (res) outres[(size_t)node * DD + col] =
                __fadd_rn(m, res[(size_t)node * DD + col]);
        }
    }
}

// ---------------- fast aligned SGEMM (FMA2, R13 core) ----------------------
__global__ __launch_bounds__(256) void sgemm_fast(
    const float* __restrict__ A, const float* __restrict__ B,
    const float* __restrict__ bias, float* __restrict__ C,
    int N, int K, int do_relu)
{
    __shared__ float As[2][FBK][SPAD];
    __shared__ float Bs[2][FBK][SPAD];
    int tid = threadIdx.x;
    int tx = tid & 15, ty = tid >> 4;
    int lr = tid >> 1, lk = (tid & 1) * 8;
    int brow = tid >> 4, bc = (tid & 15) * 8;
    int row0 = blockIdx.y * 128, col0 = blockIdx.x * 128;

    const float* ap = A + (size_t)(row0 + lr) * K + lk;
    const float* bp = B + (size_t)brow * N + col0 + bc;

    unsigned long long acc2[8][4];
#pragma unroll
    for (int i = 0; i < 8; i++)
#pragma unroll
        for (int j = 0; j < 4; j++) acc2[i][j] = 0ULL;

    float pa[8], pb[8];
    ld8(ap, pa); ld8(bp, pb);
#pragma unroll
    for (int i = 0; i < 8; i++) As[0][lk + i][lr] = pa[i];
    *(float4*)&Bs[0][brow][bc]     = make_float4(pb[0], pb[1], pb[2], pb[3]);
    *(float4*)&Bs[0][brow][bc + 4] = make_float4(pb[4], pb[5], pb[6], pb[7]);
    __syncthreads();

    int buf = 0;
    for (int k0 = 0; k0 < K; k0 += FBK, buf ^= 1) {
        int kn = k0 + FBK;
        if (kn < K) { ld8(ap + kn, pa); ld8(bp + (size_t)kn * N, pb); }
        if (buf == 0) { COMPUTE_TILE2(As[0], Bs[0]); } else { COMPUTE_TILE2(As[1], Bs[1]); }
        if (kn < K) {
#pragma unroll
            for (int i = 0; i < 8; i++) As[buf ^ 1][lk + i][lr] = pa[i];
            *(float4*)&Bs[buf ^ 1][brow][bc]     = make_float4(pb[0], pb[1], pb[2], pb[3]);
            *(float4*)&Bs[buf ^ 1][brow][bc + 4] = make_float4(pb[4], pb[5], pb[6], pb[7]);
            __syncthreads();
        }
    }

#pragma unroll
    for (int i = 0; i < 8; i++) {
        int r = row0 + ty * 8 + i;
#pragma unroll
        for (int j4 = 0; j4 < 4; j4++) {
            float v0, v1;
            UNPACK2(v0, v1, acc2[i][j4]);
            int c0 = col0 + tx * 8 + 2 * j4;
            if (bias) {
                v0 = __fadd_rn(v0, bias[c0]);
                v1 = __fadd_rn(v1, bias[c0 + 1]);
            }
            if (do_relu) { v0 = fmaxf(v0, 0.f); v1 = fmaxf(v1, 0.f); }
            C[(size_t)r * N + c0]     = v0;
            C[(size_t)r * N + c0 + 1] = v1;
        }
    }
}

// ---------------- general SGEMM (bounds-checked; only K=3 coords layer) ----
#define BK 8
__global__ __launch_bounds__(256) void sgemm_nn(
    const float* __restrict__ A, const float* __restrict__ B,
    const float* __restrict__ bias, float* __restrict__ C,
    int M, int N, int K, int do_relu)
{
    __shared__ float As[BK][128];
    __shared__ float Bs[BK][128];
    int tid = threadIdx.x;
    int row0 = blockIdx.y * 128;
    int col0 = blockIdx.x * 128;
    int tx = tid & 15, ty = tid >> 4;
    int arow = tid >> 1, ac0 = (tid & 1) * 4;
    int brow = tid >> 5, bc0 = (tid & 31) * 4;

    float acc[8][8];
#pragma unroll
    for (int i = 0; i < 8; i++)
#pragma unroll
        for (int j = 0; j < 8; j++) acc[i][j] = 0.f;

    for (int k0 = 0; k0 < K; k0 += BK) {
#pragma unroll
        for (int i = 0; i < 4; i++) {
            int gr = row0 + arow, gc = k0 + ac0 + i;
            As[ac0 + i][arow] = (gr < M && gc < K) ? A[(size_t)gr * K + gc] : 0.f;
        }
#pragma unroll
        for (int i = 0; i < 4; i++) {
            int gr = k0 + brow, gc = col0 + bc0 + i;
            Bs[brow][bc0 + i] = (gr < K && gc < N) ? B[(size_t)gr * N + gc] : 0.f;
        }
        __syncthreads();
#pragma unroll
        for (int kk = 0; kk < BK; kk++) {
            float a[8], b[8];
#pragma unroll
            for (int i = 0; i < 8; i++) a[i] = As[kk][ty * 8 + i];
#pragma unroll
            for (int j = 0; j < 8; j++) b[j] = Bs[kk][tx * 8 + j];
#pragma unroll
            for (int i = 0; i < 8; i++)
#pragma unroll
                for (int j = 0; j < 8; j++)
                    acc[i][j] = fmaf(a[i], b[j], acc[i][j]);
        }
        __syncthreads();
    }

#pragma unroll
    for (int i = 0; i < 8; i++) {
        int r = row0 + ty * 8 + i;
        if (r >= M) continue;
#pragma unroll
        for (int j = 0; j < 8; j++) {
            int c = col0 + tx * 8 + j;
            if (c >= N) continue;
            float vv = acc[i][j];
            if (bias) vv = __fadd_rn(vv, bias[c]);
            if (do_relu) vv = fmaxf(vv, 0.f);
            C[(size_t)r * N + c] = vv;
        }
    }
}

// ---------------- row squared norm (same rounding tree, 16 threads/row) ----
__global__ void row_sq_cpu(const float* __restrict__ x, float* __restrict__ sq, int K)
{
    int g = blockIdx.x * 256 + threadIdx.x;
    int row = g >> 4;
    if (row >= NROWS) return;
    int j = g & 15;
    const float* xr = x + (size_t)row * K;
    float a = 0.f;
    for (int i = 0; i < K; i += 16) {
        float v = xr[i + j];
        a = __fadd_rn(a, __fmul_rn(v, v));
    }
    unsigned lane = threadIdx.x & 31;
    unsigned base = lane & 16u;
    float b1 = __shfl_sync(0xffffffffu, a, base + ((j + 4) & 15));
    float b2 = __shfl_sync(0xffffffffu, a, base + ((j + 8) & 15));
    float b3 = __shfl_sync(0xffffffffu, a, base + ((j + 12) & 15));
    float t = __fadd_rn(__fadd_rn(__fadd_rn(a, b1), b2), b3);
    float tp = __shfl_sync(0xffffffffu, t, base + ((j + 2) & 15));
    float u = __fadd_rn(t, tp);
    float up = __shfl_sync(0xffffffffu, u, base + 1);
    if (j == 0) sq[row] = __fadd_rn(u, up);
}

// ---------------- top-16 smallest per row (one warp per row, proven) -------
__global__ __launch_bounds__(256) void knn_topk(
    const float* __restrict__ dist, int* __restrict__ idx)
{
    int gw = (blockIdx.x * 256 + threadIdx.x) >> 5;
    int lane = threadIdx.x & 31;
    if (gw >= NROWS) return;
    const float* dr = dist + (size_t)gw * NPTS;

    float ld[KNN]; int li[KNN];
#pragma unroll
    for (int i = 0; i < KNN; i++) { ld[i] = FLT_MAX; li[i] = 0x7fffffff; }

    for (int j = lane; j < NPTS; j += 32) {
        float d = dr[j];
        if (d < ld[KNN - 1]) {
            ld[KNN - 1] = d; li[KNN - 1] = j;
#pragma unroll
            for (int p = KNN - 1; p > 0; p--) {
                if (ld[p] < ld[p - 1]) {
                    float tf = ld[p]; ld[p] = ld[p - 1]; ld[p - 1] = tf;
                    int ti = li[p]; li[p] = li[p - 1]; li[p - 1] = ti;
                }
            }
        }
    }

    int* orow = idx + gw * KNN;
    for (int t = 0; t < KNN; t++) {
        float mv = ld[0]; int mi = li[0];
#pragma unroll
        for (int o = 16; o; o >>= 1) {
            float ov = __shfl_xor_sync(0xffffffffu, mv, o);
            int   oi = __shfl_xor_sync(0xffffffffu, mi, o);
            if (ov < mv || (ov == mv && oi < mi)) { mv = ov; mi = oi; }
        }
        if (lane == 0) orow[t] = mi;
        if (li[0] == mi) {
#pragma unroll
            for (int p = 0; p < KNN - 1; p++) { ld[p] = ld[p + 1]; li[p] = li[p + 1]; }
            ld[KNN - 1] = FLT_MAX; li[KNN - 1] = 0x7fffffff;
        }
    }
}

// ---------------- u/v aggregation for the FINAL conv (selection-free) ------
// out[n][d] = max_t relu(u1[n][d] + (v[src][d]-v[n][d]) + b[d]). Rounding
// differs from the literal edge chain by ~1e-5 relative, but this conv's
// output feeds only dense heads (no further kNN), so it propagates
// continuously. (Validated R15: rel_err 9.55e-7.)
__global__ __launch_bounds__(256) void ec_agg_uv(
    const float* __restrict__ u1, const float* __restrict__ v,
    const float* __restrict__ bias, const int* __restrict__ idx,
    float* __restrict__ out, const float* __restrict__ res,
    float* __restrict__ outres)
{
    int row = blockIdx.x;
    int d = threadIdx.x;
    int bb = (row >> 12) << 12;
    __shared__ int sidx[KNN];
    if (d < KNN) sidx[d] = idx[row * KNN + d] + bb;
    __syncthreads();
    float vn = v[(size_t)row * DD + d];
    float uu = u1[(size_t)row * DD + d];
    float bd = bias[d];
    float m = -FLT_MAX;
#pragma unroll
    for (int t = 0; t < KNN; t++) {
        float vs = v[(size_t)sidx[t] * DD + d];
        float h = fmaxf(__fadd_rn(__fadd_rn(uu, __fsub_rn(vs, vn)), bd), 0.f);
        m = fmaxf(m, h);
    }
    out[(size_t)row * DD + d] = m;
    if (res) outres[(size_t)row * DD + d] = __fadd_rn(m, res[(size_t)row * DD + d]);
}

// ---------------- concat [x2(256) | feat(512) | joint(16)] ------------------
__global__ void concat_kernel(const float* __restrict__ x2, const float* __restrict__ feat,
                              const float* __restrict__ joint, float* __restrict__ xcat)
{
    size_t i = (size_t)blockIdx.x * 256 + threadIdx.x;
    if (i >= (size_t)NROWS * CCAT) return;
    int row = (int)(i / CCAT);
    int c = (int)(i % CCAT);
    float v;
    if (c < DD)            v = x2[(size_t)row * DD + c];
    else if (c < DD + FDIM) v = feat[(size_t)row * FDIM + (c - DD)];
    else                    v = joint[(size_t)row * JDIM + (c - DD - FDIM)];
    xcat[i] = v;
}

// ---------------- small-N head GEMM (N = 3 or 1), relu ----------------------
__global__ void head_gemm(const float* __restrict__ A, const float* __restrict__ W,
                          const float* __restrict__ bias, float* __restrict__ out, int Nout)
{
    int warp = (blockIdx.x * 256 + threadIdx.x) >> 5;
    int lane = threadIdx.x & 31;
    if (warp >= NROWS) return;
    const float* a = A + (size_t)warp * DD;
    for (int oc = 0; oc < Nout; oc++) {
        float s = 0.f;
        for (int c = lane; c < DD; c += 32) s = fmaf(a[c], W[(size_t)c * Nout + oc], s);
#pragma unroll
        for (int o = 16; o; o >>= 1) s += __shfl_xor_sync(0xffffffffu, s, o);
        if (lane == 0) out[(size_t)warp * Nout + oc] = fmaxf(__fadd_rn(s, bias[oc]), 0.f);
    }
}

// ---------------- host-side orchestration -----------------------------------
static void run_edge_conv(const float* x, int C, const float* w, const float* bias,
                          float* sq, float* dist, int* idx, float* u1, float* v,
                          float* out, const float* res, float* outres, int use_uv)
{
    sgemm_fast<<<dim3(DD / 128, NROWS / 128), 256>>>(x, w, nullptr, u1, DD, C, 0);
    row_sq_cpu<<<NROWS * 16 / 256, 256>>>(x, sq, C);
    dist_sym<<<dim3(32, 32, BATCH), 256>>>(x, sq, dist, C);
    knn_topk<<<NROWS * 32 / 256, 256>>>(dist, idx);
    if (use_uv) {
        sgemm_fast<<<dim3(DD / 128, NROWS / 128), 256>>>(
            x, w + (size_t)C * DD, nullptr, v, DD, C, 0);
        ec_agg_uv<<<NROWS, 256>>>(u1, v, bias, idx, out, res, outres);
    } else {
        hgemm_max<<<dim3(DD / 128, NEDGE / 128), 256>>>(
            x, w + (size_t)C * DD, bias, u1, idx, out, res, outres, C);
    }
}

extern "C" void kernel_launch(void* const* d_in, const int* in_sizes, int n_in,
                              void* d_out, int out_size)
{
    const float* coords = (const float*)d_in[0];
    const float* feat   = (const float*)d_in[1];
    const float* joint  = (const float*)d_in[2];
    const float* w_h1 = (const float*)d_in[3];  const float* b_h1 = (const float*)d_in[4];
    const float* w_h2 = (const float*)d_in[5];  const float* b_h2 = (const float*)d_in[6];
    const float* w_e1 = (const float*)d_in[7];  const float* b_e1 = (const float*)d_in[8];
    const float* w_e2 = (const float*)d_in[9];  const float* b_e2 = (const float*)d_in[10];
    const float* w_h3 = (const float*)d_in[11]; const float* b_h3 = (const float*)d_in[12];
    const float* w_c1 = (const float*)d_in[13]; const float* b_c1 = (const float*)d_in[14];
    const float* w_c2 = (const float*)d_in[15]; const float* b_c2 = (const float*)d_in[16];
    const float* w_c3 = (const float*)d_in[17]; const float* b_c3 = (const float*)d_in[18];
    const float* w_h4 = (const float*)d_in[19]; const float* b_h4 = (const float*)d_in[20];
    const float* w_o1 = (const float*)d_in[21]; const float* b_o1 = (const float*)d_in[22];
    const float* w_h5 = (const float*)d_in[23]; const float* b_h5 = (const float*)d_in[24];
    const float* w_o2 = (const float*)d_in[25]; const float* b_o2 = (const float*)d_in[26];
    float* out = (float*)d_out;

    void* p;
    cudaGetSymbolAddress(&p, g_dist); float* dist = (float*)p;
    cudaGetSymbolAddress(&p, g_xcat); float* xcat = (float*)p;
    cudaGetSymbolAddress(&p, g_u1);   float* u1   = (float*)p;
    cudaGetSymbolAddress(&p, g_v);    float* v    = (float*)p;
    cudaGetSymbolAddress(&p, g_sq);   float* sq   = (float*)p;
    cudaGetSymbolAddress(&p, g_idx);  int*   idx  = (int*)p;
    cudaGetSymbolAddress(&p, g_b0);   float* b0   = (float*)p;
    cudaGetSymbolAddress(&p, g_b1);   float* b1   = (float*)p;
    cudaGetSymbolAddress(&p, g_b2);   float* b2   = (float*)p;
    cudaGetSymbolAddress(&p, g_b3);   float* b3   = (float*)p;
    cudaGetSymbolAddress(&p, g_b4);   float* b4   = (float*)p;
    cudaGetSymbolAddress(&p, g_b5);   float* b5   = (float*)p;

    // x1 = relu(coords @ w_h1 + b_h1) ; x2 = relu(x1 @ w_h2 + b_h2)
    sgemm_nn<<<dim3(2, 64), 256>>>(coords, w_h1, b_h1, b0, NROWS, DD, 3, 1);
    sgemm_fast<<<dim3(2, 64), 256>>>(b0, w_h2, b_h2, b1, DD, DD, 1);

    // xcat = [x2 | feat | joint]  (8192 x 784)
    concat_kernel<<<(int)(((size_t)NROWS * CCAT + 255) / 256), 256>>>(b1, feat, joint, xcat);

    // EdgeConvE 1 (C=784) -> b0
    run_edge_conv(xcat, CCAT, w_e1, b_e1, sq, dist, idx, u1, v, b0, nullptr, nullptr, 0);
    // EdgeConvE 2 (C=256) -> b1
    run_edge_conv(b0, DD, w_e2, b_e2, sq, dist, idx, u1, v, b1, nullptr, nullptr, 0);

    // x3 = relu(b1 @ w_h3 + b_h3) -> b2
    sgemm_fast<<<dim3(2, 64), 256>>>(b1, w_h3, b_h3, b2, DD, DD, 1);

    // e1 = edgeconv(x3, c1) -> b3
    run_edge_conv(b2, DD, w_c1, b_c1, sq, dist, idx, u1, v, b3, nullptr, nullptr, 0);
    // e2 = edgeconv(e1, c2) -> b4 ; xa = e2 + e1 -> b5
    run_edge_conv(b3, DD, w_c2, b_c2, sq, dist, idx, u1, v, b4, b3, b5, 0);
    // e3 = edgeconv(xa, c3) -> b2 ; xb = e3 + e2 -> b0   (FINAL conv: u/v ok)
    run_edge_conv(b5, DD, w_c3, b_c3, sq, dist, idx, u1, v, b2, b4, b0, 1);

    // out1 = relu(relu(xb @ w_h4 + b_h4) @ w_o1 + b_o1)   [8192 x 3]
    sgemm_fast<<<dim3(2, 64), 256>>>(b0, w_h4, b_h4, b1, DD, DD, 1);
    head_gemm<<<NROWS * 32 / 256, 256>>>(b1, w_o1, b_o1, out, 3);

    // out2 = relu(relu(xb @ w_h5 + b_h5) @ w_o2 + b_o2)   [8192 x 1]
    sgemm_fast<<<dim3(2, 64), 256>>>(b0, w_h5, b_h5, b3, DD, DD, 1);
    head_gemm<<<NROWS * 32 / 256, 256>>>(b3, w_o2, b_o2, out + (size_t)NROWS * 3, 1);
}

// round 17
// speedup vs baseline: 1.1902x; 1.0174x over previous
#include <cuda_runtime.h>
#include <cfloat>
#include <cstdint>

// Problem constants
#define BATCH 2
#define NPTS  4096
#define NROWS (BATCH * NPTS)   // 8192
#define DD    256
#define CCAT  784              // 256 + 512 + 16
#define FDIM  512
#define JDIM  16
#define KNN   16
#define NEDGE (NROWS * KNN)    // 131072

#define FBK  16
#define SPAD 132

// ---------------- scratch (device globals; no allocation allowed) ----------
__device__ float g_dist[(size_t)BATCH * NPTS * NPTS];   // 134 MB
__device__ float g_xcat[(size_t)NROWS * CCAT];
__device__ float g_u1[(size_t)NROWS * DD];
__device__ float g_v[(size_t)NROWS * DD];
__device__ float g_sq[NROWS];
__device__ int   g_idx[NROWS * KNN];
__device__ float g_b0[(size_t)NROWS * DD];
__device__ float g_b1[(size_t)NROWS * DD];
__device__ float g_b2[(size_t)NROWS * DD];
__device__ float g_b3[(size_t)NROWS * DD];
__device__ float g_b4[(size_t)NROWS * DD];
__device__ float g_b5[(size_t)NROWS * DD];

// ---------------- tile-load helpers ----------------------------------------
__device__ __forceinline__ void ld8(const float* p, float* r) {
    float4 v0 = *(const float4*)p;
    float4 v1 = *(const float4*)(p + 4);
    r[0] = v0.x; r[1] = v0.y; r[2] = v0.z; r[3] = v0.w;
    r[4] = v1.x; r[5] = v1.y; r[6] = v1.z; r[7] = v1.w;
}
__device__ __forceinline__ void ld8_diff(const float* ps, const float* pn, float* r) {
    float4 s0 = *(const float4*)ps;
    float4 s1 = *(const float4*)(ps + 4);
    float4 n0 = *(const float4*)pn;
    float4 n1 = *(const float4*)(pn + 4);
    r[0] = __fsub_rn(s0.x, n0.x); r[1] = __fsub_rn(s0.y, n0.y);
    r[2] = __fsub_rn(s0.z, n0.z); r[3] = __fsub_rn(s0.w, n0.w);
    r[4] = __fsub_rn(s1.x, n1.x); r[5] = __fsub_rn(s1.y, n1.y);
    r[6] = __fsub_rn(s1.z, n1.z); r[7] = __fsub_rn(s1.w, n1.w);
}

#define UNPACK2(lo, hi, v) \
    asm("mov.b64 {%0, %1}, %2;" : "=f"(lo), "=f"(hi) : "l"(v))

// FMA2 inner-product step (R13 proven core): A scalar in smem, duplicated
// into both lanes via mov.b64 (ALU pipe, parallel to FMA pipe). acc2[i][j4]
// packs output columns (2*j4, 2*j4+1). Lane-wise IEEE rn — bit-identical to
// scalar fmaf chains, K ascending.
#define COMPUTE_TILE2(AsB, BsB)                                               \
    _Pragma("unroll")                                                         \
    for (int kk = 0; kk < FBK; kk++) {                                        \
        float4 av0 = *(const float4*)&AsB[kk][ty * 8];                        \
        float4 av1 = *(const float4*)&AsB[kk][ty * 8 + 4];                    \
        ulonglong2 bq0 = *(const ulonglong2*)&BsB[kk][tx * 8];                \
        ulonglong2 bq1 = *(const ulonglong2*)&BsB[kk][tx * 8 + 4];            \
        unsigned long long bb[4] = {bq0.x, bq0.y, bq1.x, bq1.y};              \
        float a[8] = {av0.x, av0.y, av0.z, av0.w, av1.x, av1.y, av1.z, av1.w};\
        _Pragma("unroll")                                                     \
        for (int i = 0; i < 8; i++) {                                         \
            unsigned long long ad;                                            \
            asm("mov.b64 %0, {%1, %1};" : "=l"(ad) : "f"(a[i]));              \
            _Pragma("unroll")                                                 \
            for (int j = 0; j < 4; j++)                                       \
                asm("fma.rn.f32x2 %0, %1, %2, %0;"                            \
                    : "+l"(acc2[i][j]) : "l"(ad), "l"(bb[j]));                \
        }                                                                     \
    }

// ---------------- symmetric dist GEMM (FMA2, single-sync double buffer) ----
__global__ __launch_bounds__(256) void dist_sym(
    const float* __restrict__ X, const float* __restrict__ sq,
    float* __restrict__ dist, int K)
{
    int bx = blockIdx.x, by = blockIdx.y;
    if (by > bx) return;
    const float* Xb  = X  + (size_t)blockIdx.z * NPTS * K;
    const float* sqb = sq + (size_t)blockIdx.z * NPTS;
    float* db        = dist + (size_t)blockIdx.z * NPTS * NPTS;

    __shared__ float As[2][FBK][SPAD];
    __shared__ float Bs[2][FBK][SPAD];
    int tid = threadIdx.x;
    int tx = tid & 15, ty = tid >> 4;
    int lr = tid >> 1, lk = (tid & 1) * 8;
    int row0 = by * 128, col0 = bx * 128;

    const float* ap = Xb + (size_t)(row0 + lr) * K + lk;
    const float* bp = Xb + (size_t)(col0 + lr) * K + lk;

    unsigned long long acc2[8][4];
#pragma unroll
    for (int i = 0; i < 8; i++)
#pragma unroll
        for (int j = 0; j < 4; j++) acc2[i][j] = 0ULL;

    float pa[8], pb[8];
    ld8(ap, pa); ld8(bp, pb);
#pragma unroll
    for (int i = 0; i < 8; i++) { As[0][lk + i][lr] = pa[i]; Bs[0][lk + i][lr] = pb[i]; }
    __syncthreads();

    int buf = 0;
    for (int k0 = 0; k0 < K; k0 += FBK, buf ^= 1) {
        int kn = k0 + FBK;
        if (kn < K) { ld8(ap + kn, pa); ld8(bp + kn, pb); }
        if (buf == 0) { COMPUTE_TILE2(As[0], Bs[0]); } else { COMPUTE_TILE2(As[1], Bs[1]); }
        if (kn < K) {
#pragma unroll
            for (int i = 0; i < 8; i++) {
                As[buf ^ 1][lk + i][lr] = pa[i];
                Bs[buf ^ 1][lk + i][lr] = pb[i];
            }
            __syncthreads();
        }
    }

#pragma unroll
    for (int i = 0; i < 8; i++) {
        int r = row0 + ty * 8 + i;
        float sr = sqb[r];
#pragma unroll
        for (int j4 = 0; j4 < 4; j4++) {
            float d0, d1;
            UNPACK2(d0, d1, acc2[i][j4]);
            int c0 = col0 + tx * 8 + 2 * j4;
            float sc0 = sqb[c0], sc1 = sqb[c0 + 1];
            float t0 = __fmul_rn(2.f, d0), t1 = __fmul_rn(2.f, d1);
            db[(size_t)r * NPTS + c0]     = __fadd_rn(__fsub_rn(sr, t0), sc0);
            db[(size_t)r * NPTS + c0 + 1] = __fadd_rn(__fsub_rn(sr, t1), sc1);
            db[(size_t)c0 * NPTS + r]       = __fadd_rn(__fsub_rn(sc0, t0), sr);
            db[(size_t)(c0 + 1) * NPTS + r] = __fadd_rn(__fsub_rn(sc1, t1), sr);
        }
    }
}

// ---------------- edge H-GEMM: fused gather + u1 init + bias/relu/16-max ---
__global__ __launch_bounds__(256) void hgemm_max(
    const float* __restrict__ x, const float* __restrict__ W2,
    const float* __restrict__ bias, const float* __restrict__ u1,
    const int* __restrict__ idx,
    float* __restrict__ out, const float* __restrict__ res,
    float* __restrict__ outres, int K)
{
    __shared__ float As[2][FBK][SPAD];
    __shared__ float Bs[2][FBK][SPAD];
    __shared__ float pm[16][128];

    int tid = threadIdx.x;
    int tx = tid & 15, ty = tid >> 4;
    int lr = tid >> 1, lk = (tid & 1) * 8;
    int brow = tid >> 4, bc = (tid & 15) * 8;
    int row0 = blockIdx.y * 128;       // edge rows
    int col0 = blockIdx.x * 128;       // output channels

    int erow = row0 + lr;
    int nodeA = erow >> 4, tA = erow & 15;
    int bb2 = (nodeA >> 12) << 12;
    int srcA = bb2 + idx[nodeA * KNN + tA];
    const float* aps = x + (size_t)srcA * K + lk;
    const float* apn = x + (size_t)nodeA * K + lk;
    const float* bp  = W2 + (size_t)brow * DD + col0 + bc;

    unsigned long long acc2[8][4];
#pragma unroll
    for (int i = 0; i < 8; i++) {
        int node = (row0 + ty * 8 + i) >> 4;
        const unsigned long long* up =
            (const unsigned long long*)&u1[(size_t)node * DD + col0 + tx * 8];
#pragma unroll
        for (int j = 0; j < 4; j++) acc2[i][j] = up[j];
    }

    float pa[8], pb[8];
    ld8_diff(aps, apn, pa);
    ld8(bp, pb);
#pragma unroll
    for (int i = 0; i < 8; i++) As[0][lk + i][lr] = pa[i];
    *(float4*)&Bs[0][brow][bc]     = make_float4(pb[0], pb[1], pb[2], pb[3]);
    *(float4*)&Bs[0][brow][bc + 4] = make_float4(pb[4], pb[5], pb[6], pb[7]);
    __syncthreads();

    int buf = 0;
    for (int k0 = 0; k0 < K; k0 += FBK, buf ^= 1) {
        int kn = k0 + FBK;
        if (kn < K) {
            ld8_diff(aps + kn, apn + kn, pa);
            ld8(bp + (size_t)kn * DD, pb);
        }
        if (buf == 0) { COMPUTE_TILE2(As[0], Bs[0]); } else { COMPUTE_TILE2(As[1], Bs[1]); }
        if (kn < K) {
#pragma unroll
            for (int i = 0; i < 8; i++) As[buf ^ 1][lk + i][lr] = pa[i];
            *(float4*)&Bs[buf ^ 1][brow][bc]     = make_float4(pb[0], pb[1], pb[2], pb[3]);
            *(float4*)&Bs[buf ^ 1][brow][bc + 4] = make_float4(pb[4], pb[5], pb[6], pb[7]);
            __syncthreads();
        }
    }

    // epilogue: +bias (rounded), relu, per-thread max over own 8 edge rows
#pragma unroll
    for (int j4 = 0; j4 < 4; j4++) {
        int cc0 = tx * 8 + 2 * j4;
        float b0v = bias[col0 + cc0], b1v = bias[col0 + cc0 + 1];
        float mx0 = -FLT_MAX, mx1 = -FLT_MAX;
#pragma unroll
        for (int i = 0; i < 8; i++) {
            float h0, h1;
            UNPACK2(h0, h1, acc2[i][j4]);
            h0 = fmaxf(__fadd_rn(h0, b0v), 0.f);
            h1 = fmaxf(__fadd_rn(h1, b1v), 0.f);
            mx0 = fmaxf(mx0, h0);
            mx1 = fmaxf(mx1, h1);
        }
        pm[ty][cc0] = mx0;
        pm[ty][cc0 + 1] = mx1;
    }
    __syncthreads();
    if ((ty & 1) == 0) {
        int node = (row0 >> 4) + (ty >> 1);
#pragma unroll
        for (int j = 0; j < 8; j++) {
            int cc = tx * 8 + j;
            float m = fmaxf(pm[ty][cc], pm[ty + 1][cc]);
            int col = col0 + cc;
            out[(size_t)node * DD + col] = m;
            if (res) outres[(size_t)node * DD + col] =
                __fadd_rn(m, res[(size_t)node * DD + col]);
        }
    }
}

// ---------------- fast aligned SGEMM (FMA2, R13 core) ----------------------
__global__ __launch_bounds__(256) void sgemm_fast(
    const float* __restrict__ A, const float* __restrict__ B,
    const float* __restrict__ bias, float* __restrict__ C,
    int N, int K, int do_relu)
{
    __shared__ float As[2][FBK][SPAD];
    __shared__ float Bs[2][FBK][SPAD];
    int tid = threadIdx.x;
    int tx = tid & 15, ty = tid >> 4;
    int lr = tid >> 1, lk = (tid & 1) * 8;
    int brow = tid >> 4, bc = (tid & 15) * 8;
    int row0 = blockIdx.y * 128, col0 = blockIdx.x * 128;

    const float* ap = A + (size_t)(row0 + lr) * K + lk;
    const float* bp = B + (size_t)brow * N + col0 + bc;

    unsigned long long acc2[8][4];
#pragma unroll
    for (int i = 0; i < 8; i++)
#pragma unroll
        for (int j = 0; j < 4; j++) acc2[i][j] = 0ULL;

    float pa[8], pb[8];
    ld8(ap, pa); ld8(bp, pb);
#pragma unroll
    for (int i = 0; i < 8; i++) As[0][lk + i][lr] = pa[i];
    *(float4*)&Bs[0][brow][bc]     = make_float4(pb[0], pb[1], pb[2], pb[3]);
    *(float4*)&Bs[0][brow][bc + 4] = make_float4(pb[4], pb[5], pb[6], pb[7]);
    __syncthreads();

    int buf = 0;
    for (int k0 = 0; k0 < K; k0 += FBK, buf ^= 1) {
        int kn = k0 + FBK;
        if (kn < K) { ld8(ap + kn, pa); ld8(bp + (size_t)kn * N, pb); }
        if (buf == 0) { COMPUTE_TILE2(As[0], Bs[0]); } else { COMPUTE_TILE2(As[1], Bs[1]); }
        if (kn < K) {
#pragma unroll
            for (int i = 0; i < 8; i++) As[buf ^ 1][lk + i][lr] = pa[i];
            *(float4*)&Bs[buf ^ 1][brow][bc]     = make_float4(pb[0], pb[1], pb[2], pb[3]);
            *(float4*)&Bs[buf ^ 1][brow][bc + 4] = make_float4(pb[4], pb[5], pb[6], pb[7]);
            __syncthreads();
        }
    }

#pragma unroll
    for (int i = 0; i < 8; i++) {
        int r = row0 + ty * 8 + i;
#pragma unroll
        for (int j4 = 0; j4 < 4; j4++) {
            float v0, v1;
            UNPACK2(v0, v1, acc2[i][j4]);
            int c0 = col0 + tx * 8 + 2 * j4;
            if (bias) {
                v0 = __fadd_rn(v0, bias[c0]);
                v1 = __fadd_rn(v1, bias[c0 + 1]);
            }
            if (do_relu) { v0 = fmaxf(v0, 0.f); v1 = fmaxf(v1, 0.f); }
            C[(size_t)r * N + c0]     = v0;
            C[(size_t)r * N + c0 + 1] = v1;
        }
    }
}

// ---------------- general SGEMM (bounds-checked; only K=3 coords layer) ----
#define BK 8
__global__ __launch_bounds__(256) void sgemm_nn(
    const float* __restrict__ A, const float* __restrict__ B,
    const float* __restrict__ bias, float* __restrict__ C,
    int M, int N, int K, int do_relu)
{
    __shared__ float As[BK][128];
    __shared__ float Bs[BK][128];
    int tid = threadIdx.x;
    int row0 = blockIdx.y * 128;
    int col0 = blockIdx.x * 128;
    int tx = tid & 15, ty = tid >> 4;
    int arow = tid >> 1, ac0 = (tid & 1) * 4;
    int brow = tid >> 5, bc0 = (tid & 31) * 4;

    float acc[8][8];
#pragma unroll
    for (int i = 0; i < 8; i++)
#pragma unroll
        for (int j = 0; j < 8; j++) acc[i][j] = 0.f;

    for (int k0 = 0; k0 < K; k0 += BK) {
#pragma unroll
        for (int i = 0; i < 4; i++) {
            int gr = row0 + arow, gc = k0 + ac0 + i;
            As[ac0 + i][arow] = (gr < M && gc < K) ? A[(size_t)gr * K + gc] : 0.f;
        }
#pragma unroll
        for (int i = 0; i < 4; i++) {
            int gr = k0 + brow, gc = col0 + bc0 + i;
            Bs[brow][bc0 + i] = (gr < K && gc < N) ? B[(size_t)gr * N + gc] : 0.f;
        }
        __syncthreads();
#pragma unroll
        for (int kk = 0; kk < BK; kk++) {
            float a[8], b[8];
#pragma unroll
            for (int i = 0; i < 8; i++) a[i] = As[kk][ty * 8 + i];
#pragma unroll
            for (int j = 0; j < 8; j++) b[j] = Bs[kk][tx * 8 + j];
#pragma unroll
            for (int i = 0; i < 8; i++)
#pragma unroll
                for (int j = 0; j < 8; j++)
                    acc[i][j] = fmaf(a[i], b[j], acc[i][j]);
        }
        __syncthreads();
    }

#pragma unroll
    for (int i = 0; i < 8; i++) {
        int r = row0 + ty * 8 + i;
        if (r >= M) continue;
#pragma unroll
        for (int j = 0; j < 8; j++) {
            int c = col0 + tx * 8 + j;
            if (c >= N) continue;
            float vv = acc[i][j];
            if (bias) vv = __fadd_rn(vv, bias[c]);
            if (do_relu) vv = fmaxf(vv, 0.f);
            C[(size_t)r * N + c] = vv;
        }
    }
}

// ---------------- row squared norm (same rounding tree, 16 threads/row) ----
__global__ void row_sq_cpu(const float* __restrict__ x, float* __restrict__ sq, int K)
{
    int g = blockIdx.x * 256 + threadIdx.x;
    int row = g >> 4;
    if (row >= NROWS) return;
    int j = g & 15;
    const float* xr = x + (size_t)row * K;
    float a = 0.f;
    for (int i = 0; i < K; i += 16) {
        float v = xr[i + j];
        a = __fadd_rn(a, __fmul_rn(v, v));
    }
    unsigned lane = threadIdx.x & 31;
    unsigned base = lane & 16u;
    float b1 = __shfl_sync(0xffffffffu, a, base + ((j + 4) & 15));
    float b2 = __shfl_sync(0xffffffffu, a, base + ((j + 8) & 15));
    float b3 = __shfl_sync(0xffffffffu, a, base + ((j + 12) & 15));
    float t = __fadd_rn(__fadd_rn(__fadd_rn(a, b1), b2), b3);
    float tp = __shfl_sync(0xffffffffu, t, base + ((j + 2) & 15));
    float u = __fadd_rn(t, tp);
    float up = __shfl_sync(0xffffffffu, u, base + 1);
    if (j == 0) sq[row] = __fadd_rn(u, up);
}

// ---------------- top-16 smallest per row (one warp per row, proven) -------
__global__ __launch_bounds__(256) void knn_topk(
    const float* __restrict__ dist, int* __restrict__ idx)
{
    int gw = (blockIdx.x * 256 + threadIdx.x) >> 5;
    int lane = threadIdx.x & 31;
    if (gw >= NROWS) return;
    const float* dr = dist + (size_t)gw * NPTS;

    float ld[KNN]; int li[KNN];
#pragma unroll
    for (int i = 0; i < KNN; i++) { ld[i] = FLT_MAX; li[i] = 0x7fffffff; }

    for (int j = lane; j < NPTS; j += 32) {
        float d = dr[j];
        if (d < ld[KNN - 1]) {
            ld[KNN - 1] = d; li[KNN - 1] = j;
#pragma unroll
            for (int p = KNN - 1; p > 0; p--) {
                if (ld[p] < ld[p - 1]) {
                    float tf = ld[p]; ld[p] = ld[p - 1]; ld[p - 1] = tf;
                    int ti = li[p]; li[p] = li[p - 1]; li[p - 1] = ti;
                }
            }
        }
    }

    int* orow = idx + gw * KNN;
    for (int t = 0; t < KNN; t++) {
        float mv = ld[0]; int mi = li[0];
#pragma unroll
        for (int o = 16; o; o >>= 1) {
            float ov = __shfl_xor_sync(0xffffffffu, mv, o);
            int   oi = __shfl_xor_sync(0xffffffffu, mi, o);
            if (ov < mv || (ov == mv && oi < mi)) { mv = ov; mi = oi; }
        }
        if (lane == 0) orow[t] = mi;
        if (li[0] == mi) {
#pragma unroll
            for (int p = 0; p < KNN - 1; p++) { ld[p] = ld[p + 1]; li[p] = li[p + 1]; }
            ld[KNN - 1] = FLT_MAX; li[KNN - 1] = 0x7fffffff;
        }
    }
}

// ---------------- u/v aggregation for the FINAL conv (selection-free) ------
__global__ __launch_bounds__(256) void ec_agg_uv(
    const float* __restrict__ u1, const float* __restrict__ v,
    const float* __restrict__ bias, const int* __restrict__ idx,
    float* __restrict__ out, const float* __restrict__ res,
    float* __restrict__ outres)
{
    int row = blockIdx.x;
    int d = threadIdx.x;
    int bb = (row >> 12) << 12;
    __shared__ int sidx[KNN];
    if (d < KNN) sidx[d] = idx[row * KNN + d] + bb;
    __syncthreads();
    float vn = v[(size_t)row * DD + d];
    float uu = u1[(size_t)row * DD + d];
    float bd = bias[d];
    float m = -FLT_MAX;
#pragma unroll
    for (int t = 0; t < KNN; t++) {
        float vs = v[(size_t)sidx[t] * DD + d];
        float h = fmaxf(__fadd_rn(__fadd_rn(uu, __fsub_rn(vs, vn)), bd), 0.f);
        m = fmaxf(m, h);
    }
    out[(size_t)row * DD + d] = m;
    if (res) outres[(size_t)row * DD + d] = __fadd_rn(m, res[(size_t)row * DD + d]);
}

// ---------------- concat [x2(256) | feat(512) | joint(16)] ------------------
__global__ void concat_kernel(const float* __restrict__ x2, const float* __restrict__ feat,
                              const float* __restrict__ joint, float* __restrict__ xcat)
{
    size_t i = (size_t)blockIdx.x * 256 + threadIdx.x;
    if (i >= (size_t)NROWS * CCAT) return;
    int row = (int)(i / CCAT);
    int c = (int)(i % CCAT);
    float v;
    if (c < DD)            v = x2[(size_t)row * DD + c];
    else if (c < DD + FDIM) v = feat[(size_t)row * FDIM + (c - DD)];
    else                    v = joint[(size_t)row * JDIM + (c - DD - FDIM)];
    xcat[i] = v;
}

// ---------------- small-N head GEMM (N = 3 or 1), relu ----------------------
__global__ void head_gemm(const float* __restrict__ A, const float* __restrict__ W,
                          const float* __restrict__ bias, float* __restrict__ out, int Nout)
{
    int warp = (blockIdx.x * 256 + threadIdx.x) >> 5;
    int lane = threadIdx.x & 31;
    if (warp >= NROWS) return;
    const float* a = A + (size_t)warp * DD;
    for (int oc = 0; oc < Nout; oc++) {
        float s = 0.f;
        for (int c = lane; c < DD; c += 32) s = fmaf(a[c], W[(size_t)c * Nout + oc], s);
#pragma unroll
        for (int o = 16; o; o >>= 1) s += __shfl_xor_sync(0xffffffffu, s, o);
        if (lane == 0) out[(size_t)warp * Nout + oc] = fmaxf(__fadd_rn(s, bias[oc]), 0.f);
    }
}

// ---------------- stream/event resources (created once, outside capture) ----
static cudaStream_t g_s1;
static cudaEvent_t g_evA, g_evB;
static int g_init = 0;

// ---------------- host-side orchestration -----------------------------------
// u1 (and v) GEMMs run on side stream g_s1, overlapped with sq->dist->topk
// on the main stream; join before the consumer (hgemm / ec_agg_uv).
static void run_edge_conv(const float* x, int C, const float* w, const float* bias,
                          float* sq, float* dist, int* idx, float* u1, float* v,
                          float* out, const float* res, float* outres, int use_uv)
{
    cudaEventRecord(g_evA, 0);
    cudaStreamWaitEvent(g_s1, g_evA, 0);
    sgemm_fast<<<dim3(DD / 128, NROWS / 128), 256, 0, g_s1>>>(x, w, nullptr, u1, DD, C, 0);
    if (use_uv)
        sgemm_fast<<<dim3(DD / 128, NROWS / 128), 256, 0, g_s1>>>(
            x, w + (size_t)C * DD, nullptr, v, DD, C, 0);
    cudaEventRecord(g_evB, g_s1);

    row_sq_cpu<<<NROWS * 16 / 256, 256>>>(x, sq, C);
    dist_sym<<<dim3(32, 32, BATCH), 256>>>(x, sq, dist, C);
    knn_topk<<<NROWS * 32 / 256, 256>>>(dist, idx);

    cudaStreamWaitEvent(0, g_evB, 0);
    if (use_uv) {
        ec_agg_uv<<<NROWS, 256>>>(u1, v, bias, idx, out, res, outres);
    } else {
        hgemm_max<<<dim3(DD / 128, NEDGE / 128), 256>>>(
            x, w + (size_t)C * DD, bias, u1, idx, out, res, outres, C);
    }
}

extern "C" void kernel_launch(void* const* d_in, const int* in_sizes, int n_in,
                              void* d_out, int out_size)
{
    const float* coords = (const float*)d_in[0];
    const float* feat   = (const float*)d_in[1];
    const float* joint  = (const float*)d_in[2];
    const float* w_h1 = (const float*)d_in[3];  const float* b_h1 = (const float*)d_in[4];
    const float* w_h2 = (const float*)d_in[5];  const float* b_h2 = (const float*)d_in[6];
    const float* w_e1 = (const float*)d_in[7];  const float* b_e1 = (const float*)d_in[8];
    const float* w_e2 = (const float*)d_in[9];  const float* b_e2 = (const float*)d_in[10];
    const float* w_h3 = (const float*)d_in[11]; const float* b_h3 = (const float*)d_in[12];
    const float* w_c1 = (const float*)d_in[13]; const float* b_c1 = (const float*)d_in[14];
    const float* w_c2 = (const float*)d_in[15]; const float* b_c2 = (const float*)d_in[16];
    const float* w_c3 = (const float*)d_in[17]; const float* b_c3 = (const float*)d_in[18];
    const float* w_h4 = (const float*)d_in[19]; const float* b_h4 = (const float*)d_in[20];
    const float* w_o1 = (const float*)d_in[21]; const float* b_o1 = (const float*)d_in[22];
    const float* w_h5 = (const float*)d_in[23]; const float* b_h5 = (const float*)d_in[24];
    const float* w_o2 = (const float*)d_in[25]; const float* b_o2 = (const float*)d_in[26];
    float* out = (float*)d_out;

    if (!g_init) {
        cudaStreamCreateWithFlags(&g_s1, cudaStreamNonBlocking);
        cudaEventCreateWithFlags(&g_evA, cudaEventDisableTiming);
        cudaEventCreateWithFlags(&g_evB, cudaEventDisableTiming);
        g_init = 1;
    }

    void* p;
    cudaGetSymbolAddress(&p, g_dist); float* dist = (float*)p;
    cudaGetSymbolAddress(&p, g_xcat); float* xcat = (float*)p;
    cudaGetSymbolAddress(&p, g_u1);   float* u1   = (float*)p;
    cudaGetSymbolAddress(&p, g_v);    float* v    = (float*)p;
    cudaGetSymbolAddress(&p, g_sq);   float* sq   = (float*)p;
    cudaGetSymbolAddress(&p, g_idx);  int*   idx  = (int*)p;
    cudaGetSymbolAddress(&p, g_b0);   float* b0   = (float*)p;
    cudaGetSymbolAddress(&p, g_b1);   float* b1   = (float*)p;
    cudaGetSymbolAddress(&p, g_b2);   float* b2   = (float*)p;
    cudaGetSymbolAddress(&p, g_b3);   float* b3   = (float*)p;
    cudaGetSymbolAddress(&p, g_b4);   float* b4   = (float*)p;
    cudaGetSymbolAddress(&p, g_b5);   float* b5   = (float*)p;

    // x1 = relu(coords @ w_h1 + b_h1) ; x2 = relu(x1 @ w_h2 + b_h2)
    sgemm_nn<<<dim3(2, 64), 256>>>(coords, w_h1, b_h1, b0, NROWS, DD, 3, 1);
    sgemm_fast<<<dim3(2, 64), 256>>>(b0, w_h2, b_h2, b1, DD, DD, 1);

    // xcat = [x2 | feat | joint]  (8192 x 784)
    concat_kernel<<<(int)(((size_t)NROWS * CCAT + 255) / 256), 256>>>(b1, feat, joint, xcat);

    // EdgeConvE 1 (C=784) -> b0
    run_edge_conv(xcat, CCAT, w_e1, b_e1, sq, dist, idx, u1, v, b0, nullptr, nullptr, 0);
    // EdgeConvE 2 (C=256) -> b1
    run_edge_conv(b0, DD, w_e2, b_e2, sq, dist, idx, u1, v, b1, nullptr, nullptr, 0);

    // x3 = relu(b1 @ w_h3 + b_h3) -> b2
    sgemm_fast<<<dim3(2, 64), 256>>>(b1, w_h3, b_h3, b2, DD, DD, 1);

    // e1 = edgeconv(x3, c1) -> b3
    run_edge_conv(b2, DD, w_c1, b_c1, sq, dist, idx, u1, v, b3, nullptr, nullptr, 0);
    // e2 = edgeconv(e1, c2) -> b4 ; xa = e2 + e1 -> b5
    run_edge_conv(b3, DD, w_c2, b_c2, sq, dist, idx, u1, v, b4, b3, b5, 0);
    // e3 = edgeconv(xa, c3) -> b2 ; xb = e3 + e2 -> b0   (FINAL conv: u/v ok)
    run_edge_conv(b5, DD, w_c3, b_c3, sq, dist, idx, u1, v, b2, b4, b0, 1);

    // heads on two streams: (h5 -> o2) on s1, (h4 -> o1) on main
    cudaEventRecord(g_evA, 0);
    cudaStreamWaitEvent(g_s1, g_evA, 0);
    sgemm_fast<<<dim3(2, 64), 256, 0, g_s1>>>(b0, w_h5, b_h5, b3, DD, DD, 1);
    head_gemm<<<NROWS * 32 / 256, 256, 0, g_s1>>>(b3, w_o2, b_o2, out + (size_t)NROWS * 3, 1);
    cudaEventRecord(g_evB, g_s1);

    sgemm_fast<<<dim3(2, 64), 256>>>(b0, w_h4, b_h4, b1, DD, DD, 1);
    head_gemm<<<NROWS * 32 / 256, 256>>>(b1, w_o1, b_o1, out, 3);

    cudaStreamWaitEvent(0, g_evB, 0);
}